// round 16
// baseline (speedup 1.0000x reference)
#include <cuda_runtime.h>
#include <cuda_bf16.h>
#include <cstdint>

// Gate_33930241638461 — HMMA bf16 3-pass split router, 4x2 warp grid (32r x 32c per warp)
//   ldmatrix B-frags (halved) + cp.async 3-stage W ring + rolling A prefetch
//   logits[T,64] = x[T,1024] @ W[64,1024]^T + b
//   scores = logits + gumbel(u); top2 -> indices; softmax(top2) -> weights
// Output (f32): [ indices (T*2) | logits (T*64) | weights (T*2) ]

constexpr int D  = 1024;
constexpr int E  = 64;
constexpr int BM = 128;
constexpr int BK = 64;                    // K-chunk
constexpr int NCHUNK = D / BK;            // 16
constexpr int NKG    = NCHUNK * 4;        // 64 k-steps total
constexpr int WROW = 144;                 // padded smem row bytes (72 bf16)
constexpr int SPLIT_BYTES = E * WROW;     // 9216
constexpr int BUF_BYTES   = 2 * SPLIT_BYTES;  // hi+lo, 18432
constexpr int SMEM_DYN    = 3 * BUF_BYTES;    // 3-stage ring, 55296 (Sc alias fits)
constexpr float EPSF = 1e-9f;

// Pre-split W (bf16 hi/lo); L2-resident, read by all CTAs.
__device__ __nv_bfloat16 g_Whi[E * D];
__device__ __nv_bfloat16 g_Wlo[E * D];

__global__ void prep_kernel(const float* __restrict__ W) {
    const int base = blockIdx.x * 1024 + threadIdx.x;
    #pragma unroll
    for (int k = 0; k < 4; k++) {
        const int i = base + k * 256;
        const float w = W[i];
        const __nv_bfloat16 hi = __float2bfloat16(w);
        g_Whi[i] = hi;
        g_Wlo[i] = __float2bfloat16(w - __bfloat162float(hi));
    }
}

// ---------- helpers ----------
__device__ __forceinline__ uint32_t smem_u32(const void* p) {
    uint32_t a;
    asm("{ .reg .u64 t; cvta.to.shared.u64 t, %1; cvt.u32.u64 %0, t; }" : "=r"(a) : "l"(p));
    return a;
}
__device__ __forceinline__ void mma16816(float* c, const uint32_t* a, uint32_t b0, uint32_t b1) {
    asm volatile(
        "mma.sync.aligned.m16n8k16.row.col.f32.bf16.bf16.f32 "
        "{%0,%1,%2,%3},{%4,%5,%6,%7},{%8,%9},{%0,%1,%2,%3};"
        : "+f"(c[0]), "+f"(c[1]), "+f"(c[2]), "+f"(c[3])
        : "r"(a[0]), "r"(a[1]), "r"(a[2]), "r"(a[3]), "r"(b0), "r"(b1));
}
__device__ __forceinline__ void ldm4(uint32_t* r, uint32_t addr) {
    asm volatile("ldmatrix.sync.aligned.m8n8.x4.shared.b16 {%0,%1,%2,%3}, [%4];"
                 : "=r"(r[0]), "=r"(r[1]), "=r"(r[2]), "=r"(r[3]) : "r"(addr));
}
__device__ __forceinline__ void cp_async16(uint32_t dst, const void* src) {
    asm volatile("cp.async.cg.shared.global [%0], [%1], 16;" :: "r"(dst), "l"(src));
}
#define CP_COMMIT() asm volatile("cp.async.commit_group;" ::: "memory")
template <int N> __device__ __forceinline__ void cp_wait() {
    asm volatile("cp.async.wait_group %0;" :: "n"(N) : "memory");
}
__device__ __forceinline__ uint32_t pack_hi(float2 v, float2& res) {
    __nv_bfloat162 h = __float22bfloat162_rn(v);
    res.x = v.x - __bfloat162float(h.x);
    res.y = v.y - __bfloat162float(h.y);
    return *reinterpret_cast<uint32_t*>(&h);
}
__device__ __forceinline__ uint32_t pack_lo(float2 r) {
    __nv_bfloat162 l = __float22bfloat162_rn(r);
    return *reinterpret_cast<uint32_t*>(&l);
}

__global__ void __launch_bounds__(256, 2)
gate_kernel(const float* __restrict__ x,
            const float* __restrict__ bvec,
            const float* __restrict__ u,
            float* __restrict__ out_idx,
            float* __restrict__ out_logits,
            float* __restrict__ out_w)
{
    extern __shared__ char dsm[];          // W ring [3][hi|lo]; epilogue aliases Sc[128][66]
    __shared__ float s_bias[E];

    const int tid  = threadIdx.x;
    const int wid  = tid >> 5;
    const int lane = tid & 31;
    const int g    = lane >> 2;            // groupID
    const int t    = lane & 3;             // thread-in-group
    const int m0   = blockIdx.x * BM;
    const int rowGroup = wid >> 1;         // 0..3 -> 32 rows each
    const int colGroup = wid & 1;          // 0..1 -> 32 cols each
    const int warpRow  = m0 + rowGroup * 32;
    const uint32_t dsmB = smem_u32(dsm);

    if (tid < E) s_bias[tid] = bvec[tid];

    // ldmatrix per-lane row base within a 16-row n-tile pair
    const int mIdx = lane >> 3;
    const int mr   = lane & 7;
    const uint32_t lmBase = (uint32_t)(((mIdx >> 1) * 8 + mr) * WROW + (mIdx & 1) * 16);
    const uint32_t colBase = (uint32_t)(colGroup * 32) * WROW;

    // W chunk issue (cp.async): [64 rows][64 bf16] per split into padded rows
    auto issueW = [&](int c) {
        const uint32_t base = dsmB + (c % 3) * BUF_BYTES;
        #pragma unroll
        for (int s = 0; s < 2; s++) {
            const __nv_bfloat16* src = s ? g_Wlo : g_Whi;
            #pragma unroll
            for (int j = 0; j < 2; j++) {
                const int f = tid + j * 256;
                const int r = f >> 3;
                const int q = f & 7;
                cp_async16(base + s * SPLIT_BYTES + r * WROW + q * 16,
                           src + (size_t)r * D + c * BK + q * 8);
            }
        }
        CP_COMMIT();
    };

    // A fragment gmem bases: two m16 row-tiles at warpRow and warpRow+16
    const float* xA0 = x + (size_t)(warpRow + g) * D + 2 * t;
    const float* xA1 = xA0 + (size_t)16 * D;
    const size_t qoff[4] = { 0, (size_t)8 * D, 8, (size_t)8 * D + 8 };

    float acc[2][4][4];                    // [row-tile][n-tile][quad]
    #pragma unroll
    for (int rb = 0; rb < 2; rb++)
        #pragma unroll
        for (int n = 0; n < 4; n++)
            #pragma unroll
            for (int j = 0; j < 4; j++) acc[rb][n][j] = 0.0f;

    // rolling A buffer: slot[kg&1][rb][q] holds k-step kg fragment (16 cols)
    float2 slot[2][2][4];
    #pragma unroll
    for (int kg = 0; kg < 2; kg++)
        #pragma unroll
        for (int q = 0; q < 4; q++) {
            slot[kg][0][q] = *reinterpret_cast<const float2*>(xA0 + kg * 16 + qoff[q]);
            slot[kg][1][q] = *reinterpret_cast<const float2*>(xA1 + kg * 16 + qoff[q]);
        }
    issueW(0);

    for (int c = 0; c < NCHUNK; c++) {
        if (c + 1 < NCHUNK) { issueW(c + 1); cp_wait<1>(); }
        else                { cp_wait<0>(); }
        __syncthreads();                      // W[c] ready; ring buf (c+1)%3 free

        const uint32_t wb = dsmB + (c % 3) * BUF_BYTES;

        #pragma unroll
        for (int ks = 0; ks < 4; ks++) {
            const int sl = ks & 1;
            // convert this k-step (both row-tiles) to bf16 hi/lo
            uint32_t ahc[2][4], alc[2][4];
            #pragma unroll
            for (int rb = 0; rb < 2; rb++)
                #pragma unroll
                for (int q = 0; q < 4; q++) {
                    float2 r;
                    ahc[rb][q] = pack_hi(slot[sl][rb][q], r);
                    alc[rb][q] = pack_lo(r);
                }
            // refill slot with k-step kg+2 (distance 2 -> LDGs fly under ~48 MMAs)
            const int kgNext = c * 4 + ks + 2;
            if (kgNext < NKG) {
                const size_t off = (size_t)kgNext * 16;
                #pragma unroll
                for (int q = 0; q < 4; q++) {
                    slot[sl][0][q] = *reinterpret_cast<const float2*>(xA0 + off + qoff[q]);
                    slot[sl][1][q] = *reinterpret_cast<const float2*>(xA1 + off + qoff[q]);
                }
            }
            // 2 nt-pairs (this warp's 32 cols); each ldm4 pair feeds both row-tiles
            #pragma unroll
            for (int ntp = 0; ntp < 2; ntp++) {
                uint32_t h[4], l[4];
                const uint32_t a0 = wb + lmBase + colBase + ntp * (16 * WROW) + ks * 32;
                ldm4(h, a0);
                ldm4(l, a0 + SPLIT_BYTES);
                #pragma unroll
                for (int rb = 0; rb < 2; rb++) {
                    float* c0 = acc[rb][2 * ntp];
                    float* c1 = acc[rb][2 * ntp + 1];
                    mma16816(c0, ahc[rb], h[0], h[1]);   // hi*hi
                    mma16816(c1, ahc[rb], h[2], h[3]);
                    mma16816(c0, ahc[rb], l[0], l[1]);   // hi*lo
                    mma16816(c1, ahc[rb], l[2], l[3]);
                    mma16816(c0, alc[rb], h[0], h[1]);   // lo*hi
                    mma16816(c1, alc[rb], h[2], h[3]);
                }
            }
        }
    }

    __syncthreads();                          // W ring dead; alias as Sc[128][66]
    float* Sc = reinterpret_cast<float*>(dsm);

    // stage scores (+bias) to smem and write logits (coalesced float2)
    #pragma unroll
    for (int rb = 0; rb < 2; rb++) {
        const int wr0 = rowGroup * 32 + rb * 16 + g;
        #pragma unroll
        for (int nt = 0; nt < 4; nt++) {
            const int col = colGroup * 32 + nt * 8 + 2 * t;
            const float bx = s_bias[col], by = s_bias[col + 1];
            const float a0 = acc[rb][nt][0] + bx, a1 = acc[rb][nt][1] + by;
            const float a2 = acc[rb][nt][2] + bx, a3 = acc[rb][nt][3] + by;
            *reinterpret_cast<float2*>(&Sc[wr0 * 66 + col])       = make_float2(a0, a1);
            *reinterpret_cast<float2*>(&Sc[(wr0 + 8) * 66 + col]) = make_float2(a2, a3);
            *reinterpret_cast<float2*>(&out_logits[(size_t)(m0 + wr0) * E + col])     = make_float2(a0, a1);
            *reinterpret_cast<float2*>(&out_logits[(size_t)(m0 + wr0 + 8) * E + col]) = make_float2(a2, a3);
        }
    }
    __syncthreads();

    // epilogue: warp-per-row gumbel top-2 + softmax (R5-proven form)
    for (int r = wid; r < BM; r += 8) {
        const size_t tk = (size_t)(m0 + r);

        const float ua = u[tk * E + lane];
        const float ub = u[tk * E + lane + 32];
        const float ga = -__logf(-__logf(ua + EPSF) + EPSF);
        const float gb = -__logf(-__logf(ub + EPSF) + EPSF);
        float sa = Sc[r * 66 + lane]      + ga;
        float sb = Sc[r * 66 + lane + 32] + gb;
        int ia = lane, ib = lane + 32;

        float m1, m2; int i1, i2;
        if (sb > sa) { m1 = sb; i1 = ib; m2 = sa; i2 = ia; }
        else         { m1 = sa; i1 = ia; m2 = sb; i2 = ib; }

        #pragma unroll
        for (int off = 16; off > 0; off >>= 1) {
            const float om1 = __shfl_xor_sync(0xffffffffu, m1, off);
            const int   oi1 = __shfl_xor_sync(0xffffffffu, i1, off);
            const float om2 = __shfl_xor_sync(0xffffffffu, m2, off);
            const int   oi2 = __shfl_xor_sync(0xffffffffu, i2, off);
            const bool mine_first = (m1 > om1) || (m1 == om1 && i1 < oi1);
            float n1, n2; int ni1, ni2;
            if (mine_first) {
                n1 = m1; ni1 = i1;
                const bool cgt = (om1 > m2) || (om1 == m2 && oi1 < i2);
                if (cgt) { n2 = om1; ni2 = oi1; } else { n2 = m2; ni2 = i2; }
            } else {
                n1 = om1; ni1 = oi1;
                const bool cgt = (m1 > om2) || (m1 == om2 && i1 < oi2);
                if (cgt) { n2 = m1; ni2 = i1; } else { n2 = om2; ni2 = oi2; }
            }
            m1 = n1; i1 = ni1; m2 = n2; i2 = ni2;
        }

        if (lane == 0) {
            const float e2  = __expf(m2 - m1);   // m1 >= m2
            const float inv = 1.0f / (1.0f + e2);
            *reinterpret_cast<float2*>(&out_idx[tk * 2]) = make_float2((float)i1, (float)i2);
            *reinterpret_cast<float2*>(&out_w[tk * 2])   = make_float2(inv, e2 * inv);
        }
    }
}

extern "C" void kernel_launch(void* const* d_in, const int* in_sizes, int n_in,
                              void* d_out, int out_size)
{
    const float* x = (const float*)d_in[0];
    const float* W = (const float*)d_in[1];
    const float* b = (const float*)d_in[2];
    const float* u = (const float*)d_in[3];

    const int T = in_sizes[3] / E;   // u is [T, E]

    float* out        = (float*)d_out;
    float* out_idx    = out;                         // [T, 2]
    float* out_logits = out + (size_t)T * 2;         // [T, E]
    float* out_w      = out_logits + (size_t)T * E;  // [T, 2]

    cudaFuncSetAttribute(gate_kernel, cudaFuncAttributeMaxDynamicSharedMemorySize, SMEM_DYN);

    prep_kernel<<<E * D / 1024, 256>>>(W);           // 64 blocks
    gate_kernel<<<T / BM, 256, SMEM_DYN>>>(x, b, u, out_idx, out_logits, out_w);
}

// round 17
// speedup vs baseline: 1.6210x; 1.6210x over previous
#include <cuda_runtime.h>
#include <cuda_bf16.h>
#include <cstdint>

// Gate_33930241638461 — HMMA bf16 3-pass split router (R12 config)
//   + u-tile cp.async prefetch into dead ring buffers under the last chunk
//   logits[T,64] = x[T,1024] @ W[64,1024]^T + b
//   scores = logits + gumbel(u); top2 -> indices; softmax(top2) -> weights
// Output (f32): [ indices (T*2) | logits (T*64) | weights (T*2) ]

constexpr int D  = 1024;
constexpr int E  = 64;
constexpr int BM = 128;
constexpr int BK = 64;                    // K-chunk
constexpr int NCHUNK = D / BK;            // 16
constexpr int WROW = 144;                 // padded smem row bytes (72 bf16)
constexpr int SPLIT_BYTES = E * WROW;     // 9216
constexpr int BUF_BYTES   = 2 * SPLIT_BYTES;  // hi+lo, 18432
constexpr int SMEM_DYN    = 3 * BUF_BYTES;    // 3-stage ring, 55296
constexpr int U_SMEM_OFF  = BUF_BYTES;        // u tile (32KB) overlays bufs 1+2 (36.8KB)
constexpr float EPSF = 1e-9f;

// Pre-split W (bf16 hi/lo); L2-resident, read by all CTAs.
__device__ __nv_bfloat16 g_Whi[E * D];
__device__ __nv_bfloat16 g_Wlo[E * D];

__global__ void prep_kernel(const float* __restrict__ W) {
    const int base = blockIdx.x * 1024 + threadIdx.x;
    #pragma unroll
    for (int k = 0; k < 4; k++) {
        const int i = base + k * 256;
        const float w = W[i];
        const __nv_bfloat16 hi = __float2bfloat16(w);
        g_Whi[i] = hi;
        g_Wlo[i] = __float2bfloat16(w - __bfloat162float(hi));
    }
}

// ---------- helpers ----------
__device__ __forceinline__ uint32_t smem_u32(const void* p) {
    uint32_t a;
    asm("{ .reg .u64 t; cvta.to.shared.u64 t, %1; cvt.u32.u64 %0, t; }" : "=r"(a) : "l"(p));
    return a;
}
__device__ __forceinline__ void mma16816(float* c, const uint32_t* a, uint32_t b0, uint32_t b1) {
    asm volatile(
        "mma.sync.aligned.m16n8k16.row.col.f32.bf16.bf16.f32 "
        "{%0,%1,%2,%3},{%4,%5,%6,%7},{%8,%9},{%0,%1,%2,%3};"
        : "+f"(c[0]), "+f"(c[1]), "+f"(c[2]), "+f"(c[3])
        : "r"(a[0]), "r"(a[1]), "r"(a[2]), "r"(a[3]), "r"(b0), "r"(b1));
}
__device__ __forceinline__ void ldm4(uint32_t* r, uint32_t addr) {
    asm volatile("ldmatrix.sync.aligned.m8n8.x4.shared.b16 {%0,%1,%2,%3}, [%4];"
                 : "=r"(r[0]), "=r"(r[1]), "=r"(r[2]), "=r"(r[3]) : "r"(addr));
}
__device__ __forceinline__ void cp_async16(uint32_t dst, const void* src) {
    asm volatile("cp.async.cg.shared.global [%0], [%1], 16;" :: "r"(dst), "l"(src));
}
#define CP_COMMIT() asm volatile("cp.async.commit_group;" ::: "memory")
template <int N> __device__ __forceinline__ void cp_wait() {
    asm volatile("cp.async.wait_group %0;" :: "n"(N) : "memory");
}
__device__ __forceinline__ uint32_t pack_hi(float2 v, float2& res) {
    __nv_bfloat162 h = __float22bfloat162_rn(v);
    res.x = v.x - __bfloat162float(h.x);
    res.y = v.y - __bfloat162float(h.y);
    return *reinterpret_cast<uint32_t*>(&h);
}
__device__ __forceinline__ uint32_t pack_lo(float2 r) {
    __nv_bfloat162 l = __float22bfloat162_rn(r);
    return *reinterpret_cast<uint32_t*>(&l);
}

__global__ void __launch_bounds__(256, 2)
gate_kernel(const float* __restrict__ x,
            const float* __restrict__ bvec,
            const float* __restrict__ u,
            float* __restrict__ out_idx,
            float* __restrict__ out_logits,
            float* __restrict__ out_w)
{
    extern __shared__ char dsm[];          // W ring [3][hi|lo]; u tile overlays bufs 1+2 at the end
    __shared__ float s_bias[E];

    const int tid  = threadIdx.x;
    const int wid  = tid >> 5;
    const int lane = tid & 31;
    const int g    = lane >> 2;            // groupID
    const int t    = lane & 3;             // thread-in-group
    const int m0   = blockIdx.x * BM;
    const int warpRow = m0 + wid * 16;
    const uint32_t dsmB = smem_u32(dsm);

    if (tid < E) s_bias[tid] = bvec[tid];

    // ldmatrix per-lane row base: matrix mIdx = lane>>3 -> (nt_local = mIdx>>1, khalf = mIdx&1)
    const int mIdx = lane >> 3;
    const int mr   = lane & 7;
    const uint32_t lmBase = (uint32_t)(((mIdx >> 1) * 8 + mr) * WROW + (mIdx & 1) * 16);

    // W chunk issue (cp.async): [64 rows][64 bf16] per split into padded rows
    auto issueW = [&](int c) {
        const uint32_t base = dsmB + (c % 3) * BUF_BYTES;
        #pragma unroll
        for (int s = 0; s < 2; s++) {
            const __nv_bfloat16* src = s ? g_Wlo : g_Whi;
            #pragma unroll
            for (int j = 0; j < 2; j++) {
                const int f = tid + j * 256;
                const int r = f >> 3;
                const int q = f & 7;
                cp_async16(base + s * SPLIT_BYTES + r * WROW + q * 16,
                           src + (size_t)r * D + c * BK + q * 8);
            }
        }
        CP_COMMIT();
    };

    // A fragment gmem base: row (warpRow+g), col 2t; quad offsets per m16n8k16 A layout
    const float* xA = x + (size_t)(warpRow + g) * D + 2 * t;
    const size_t qoff[4] = { 0, (size_t)8 * D, 8, (size_t)8 * D + 8 };

    float acc[8][4];
    #pragma unroll
    for (int n = 0; n < 8; n++)
        #pragma unroll
        for (int j = 0; j < 4; j++) acc[n][j] = 0.0f;

    // preload chunk 0 A (fp32) and issue W chunk 0
    float2 acur[4][4];
    #pragma unroll
    for (int ks = 0; ks < 4; ks++)
        #pragma unroll
        for (int q = 0; q < 4; q++)
            acur[ks][q] = *reinterpret_cast<const float2*>(xA + ks * 16 + qoff[q]);
    issueW(0);

    for (int c = 0; c < NCHUNK; c++) {
        if (c + 1 < NCHUNK) { issueW(c + 1); cp_wait<1>(); }
        else                { cp_wait<0>(); }
        __syncthreads();                      // W[c] ready; ring buf (c+1)%3 free

        // Last chunk: ring bufs 1 and 2 are dead (chunk 13/14 compute done) —
        // stream this CTA's u tile (128x64 f32 = 32KB) into them under compute.
        if (c == NCHUNK - 1) {
            const float* uBase = u + (size_t)m0 * E;
            #pragma unroll
            for (int j = 0; j < 8; j++) {
                const int slot = tid + j * 256;        // 2048 float4 slots
                cp_async16(dsmB + U_SMEM_OFF + slot * 16, uBase + slot * 4);
            }
            CP_COMMIT();
        }

        const uint32_t wb = dsmB + (c % 3) * BUF_BYTES;
        const float* xn = xA + (c + 1) * BK;
        const bool pf = (c + 1 < NCHUNK);

        #pragma unroll
        for (int ks = 0; ks < 4; ks++) {
            // convert this ks fragment to bf16 hi/lo (frees acur[ks] for prefetch)
            uint32_t ahc[4], alc[4];
            #pragma unroll
            for (int q = 0; q < 4; q++) {
                float2 r;
                ahc[q] = pack_hi(acur[ks][q], r);
                alc[q] = pack_lo(r);
            }
            // prefetch next chunk's ks fragment (LDGs fly under MMAs)
            if (pf) {
                #pragma unroll
                for (int q = 0; q < 4; q++)
                    acur[ks][q] = *reinterpret_cast<const float2*>(xn + ks * 16 + qoff[q]);
            }
            // 4 nt-pairs x 3 split passes (per-acc order: hihi, hilo, lohi — R5/R12 bits)
            #pragma unroll
            for (int ntp = 0; ntp < 4; ntp++) {
                uint32_t h[4], l[4];
                const uint32_t a0 = wb + lmBase + ntp * (16 * WROW) + ks * 32;
                ldm4(h, a0);
                ldm4(l, a0 + SPLIT_BYTES);
                float* c0 = acc[2 * ntp];
                float* c1 = acc[2 * ntp + 1];
                mma16816(c0, ahc, h[0], h[1]);   // hi*hi
                mma16816(c1, ahc, h[2], h[3]);
                mma16816(c0, ahc, l[0], l[1]);   // hi*lo
                mma16816(c1, ahc, l[2], l[3]);
                mma16816(c0, alc, h[0], h[1]);   // lo*hi
                mma16816(c1, alc, h[2], h[3]);
            }
        }
    }

    // u tile landed; make it visible to all threads
    cp_wait<0>();
    __syncthreads();
    const float* uS = reinterpret_cast<const float*>(dsm + U_SMEM_OFF);  // [128][64]

    // ---- in-register epilogue: u from smem, no gmem latency on critical path ----
    // Lane (g,t) holds rows r0=warpRow+g and r0+8; cols {8nt+2t, 8nt+2t+1}.
    #pragma unroll
    for (int half = 0; half < 2; half++) {
        const int   rloc = wid * 16 + half * 8 + g;       // CTA-relative row
        const size_t tk  = (size_t)(m0 + rloc);

        float m1 = -1e30f, m2 = -1e30f;
        int   i1 = 0,      i2 = 0;

        #pragma unroll
        for (int nt = 0; nt < 8; nt++) {
            const int col = nt * 8 + 2 * t;
            const float l0 = acc[nt][half * 2 + 0] + s_bias[col];
            const float l1 = acc[nt][half * 2 + 1] + s_bias[col + 1];
            *reinterpret_cast<float2*>(&out_logits[tk * E + col]) = make_float2(l0, l1);

            const float2 uv = *reinterpret_cast<const float2*>(&uS[rloc * E + col]);
            const float s0 = l0 + (-__logf(-__logf(uv.x + EPSF) + EPSF));
            const float s1 = l1 + (-__logf(-__logf(uv.y + EPSF) + EPSF));

            // ascending col scan; strict > keeps lowest col on ties
            if (s0 > m1)      { m2 = m1; i2 = i1; m1 = s0; i1 = col; }
            else if (s0 > m2) { m2 = s0; i2 = col; }
            if (s1 > m1)      { m2 = m1; i2 = i1; m1 = s1; i1 = col + 1; }
            else if (s1 > m2) { m2 = s1; i2 = col + 1; }
        }

        // quad merge (lanes differing in bits 0-1 share the row)
        #pragma unroll
        for (int off = 1; off <= 2; off <<= 1) {
            const float om1 = __shfl_xor_sync(0xffffffffu, m1, off);
            const int   oi1 = __shfl_xor_sync(0xffffffffu, i1, off);
            const float om2 = __shfl_xor_sync(0xffffffffu, m2, off);
            const int   oi2 = __shfl_xor_sync(0xffffffffu, i2, off);
            const bool mine_first = (m1 > om1) || (m1 == om1 && i1 < oi1);
            float n1, n2; int ni1, ni2;
            if (mine_first) {
                n1 = m1; ni1 = i1;
                const bool cgt = (om1 > m2) || (om1 == m2 && oi1 < i2);
                if (cgt) { n2 = om1; ni2 = oi1; } else { n2 = m2; ni2 = i2; }
            } else {
                n1 = om1; ni1 = oi1;
                const bool cgt = (m1 > om2) || (m1 == om2 && i1 < oi2);
                if (cgt) { n2 = m1; ni2 = i1; } else { n2 = om2; ni2 = oi2; }
            }
            m1 = n1; i1 = ni1; m2 = n2; i2 = ni2;
        }

        if (t == 0) {
            const float e2  = __expf(m2 - m1);   // m1 >= m2
            const float inv = 1.0f / (1.0f + e2);
            *reinterpret_cast<float2*>(&out_idx[tk * 2]) = make_float2((float)i1, (float)i2);
            *reinterpret_cast<float2*>(&out_w[tk * 2])   = make_float2(inv, e2 * inv);
        }
    }
}

extern "C" void kernel_launch(void* const* d_in, const int* in_sizes, int n_in,
                              void* d_out, int out_size)
{
    const float* x = (const float*)d_in[0];
    const float* W = (const float*)d_in[1];
    const float* b = (const float*)d_in[2];
    const float* u = (const float*)d_in[3];

    const int T = in_sizes[3] / E;   // u is [T, E]

    float* out        = (float*)d_out;
    float* out_idx    = out;                         // [T, 2]
    float* out_logits = out + (size_t)T * 2;         // [T, E]
    float* out_w      = out_logits + (size_t)T * E;  // [T, 2]

    cudaFuncSetAttribute(gate_kernel, cudaFuncAttributeMaxDynamicSharedMemorySize, SMEM_DYN);

    prep_kernel<<<E * D / 1024, 256>>>(W);           // 64 blocks
    gate_kernel<<<T / BM, 256, SMEM_DYN>>>(x, b, u, out_idx, out_logits, out_w);
}